// round 12
// baseline (speedup 1.0000x reference)
#include <cuda_runtime.h>
#include <cuda_fp16.h>
#include <cuda_fp4.h>

// MXFP4 (E2M1) block fake-quant embedding gather — R12:
//   = R11 (tied best: 17.15us) + explicit depth-2 software pipeline on the
//     token loop + __ldcg (L2-only) row loads (no cross-token L1 reuse).
//   Model: mixed L2-latency + bandwidth bind; forcing load(j+1) before
//   process(j) guarantees the ~250cyc L2 hit latency is overlapped.
// d_in[0]: int32 indices, 16384 tokens
// d_in[1]: float32 embedding table, (50257, 1024)
// d_out  : float32 (16384, 1024)

#define F        1024
#define TOK_CTA  16

__device__ __forceinline__ float2 fp4_pair(float x, float y, float inv) {
    float2 a = make_float2(x * inv, y * inv);
    __nv_fp4x2_storage_t p =
        __nv_cvt_float2_to_fp4x2(a, __NV_E2M1, cudaRoundNearest);
    __half2_raw hr = __nv_cvt_fp4x2_to_halfraw2(p, __NV_E2M1);
    __half2 h = *reinterpret_cast<__half2*>(&hr);
    return __half22float2(h);                      // exact grid values
}

__device__ __forceinline__ float4 quant_block(float4 v) {
    // max |.| over this thread's 4 values, then the 8-lane block group
    float m = fmaxf(fmaxf(fabsf(v.x), fabsf(v.y)),
                    fmaxf(fabsf(v.z), fabsf(v.w)));
    #pragma unroll
    for (int o = 4; o > 0; o >>= 1)
        m = fmaxf(m, __shfl_xor_sync(0xFFFFFFFFu, m, o, 8));

    const float sc  = (m == 0.0f) ? 1.0f : m * (1.0f / 6.0f);
    const float inv = (m == 0.0f) ? 0.0f : __fdividef(6.0f, m);

    float2 g0 = fp4_pair(v.x, v.y, inv);
    float2 g1 = fp4_pair(v.z, v.w, inv);

    float4 r;
    r.x = g0.x * sc;
    r.y = g0.y * sc;
    r.z = g1.x * sc;
    r.w = g1.y * sc;
    return r;
}

__global__ void __launch_bounds__(256)
mxfp4_embed_kernel(const int* __restrict__ idx,
                   const float* __restrict__ emb,
                   float* __restrict__ out) {
    const int t = threadIdx.x;                      // one float4 of a row
    const int base = blockIdx.x * TOK_CTA;

    // vectorized uniform index loads (L1 broadcast): 4x LDG.128
    int rows[TOK_CTA];
    #pragma unroll
    for (int j = 0; j < TOK_CTA / 4; j++) {
        int4 r4 = __ldg(reinterpret_cast<const int4*>(idx + base) + j);
        rows[j * 4 + 0] = r4.x;
        rows[j * 4 + 1] = r4.y;
        rows[j * 4 + 2] = r4.z;
        rows[j * 4 + 3] = r4.w;
    }

    const float4* src = reinterpret_cast<const float4*>(emb);
    float4* dst = reinterpret_cast<float4*>(out) + (size_t)base * (F / 4) + t;

    // depth-2 software pipeline: load(j+1) in flight while processing j
    float4 cur = __ldcg(src + (size_t)rows[0] * (F / 4) + t);
    #pragma unroll
    for (int j = 0; j < TOK_CTA; j++) {
        float4 nxt;
        if (j + 1 < TOK_CTA)
            nxt = __ldcg(src + (size_t)rows[j + 1] * (F / 4) + t);

        float4 r = quant_block(cur);

        // streaming store: evict-first, clean writeback drain
        __stcs(dst + (size_t)j * (F / 4), r);

        cur = nxt;
    }
}

extern "C" void kernel_launch(void* const* d_in, const int* in_sizes, int n_in,
                              void* d_out, int out_size) {
    const int*   idx = (const int*)d_in[0];
    const float* emb = (const float*)d_in[1];
    float*       out = (float*)d_out;

    const int tokens = in_sizes[0];              // 16384
    mxfp4_embed_kernel<<<tokens / TOK_CTA, 256>>>(idx, emb, out);
}

// round 13
// speedup vs baseline: 1.1007x; 1.1007x over previous
#include <cuda_runtime.h>
#include <cuda_fp16.h>
#include <cuda_fp4.h>

// MXFP4 (E2M1) block fake-quant embedding gather — FINAL (= R11, 17.15us x2):
//   - gather + on-the-fly per-32-block fake-quant (never materializes the
//     full dequantized table; only referenced rows are touched)
//   - hardware E2M1 rounding: cvt.rn.satfinite.e2m1x2.f32 via cuda_fp4.h
//   - 3x shfl.xor width=8 for the 8-lane block max (R10: redux.sync with
//     divergent masks serializes — 29us regression)
//   - TOK_CTA=16 -> grid=1024: single wave on 148 SMs (R9 win)
//   - st.global.cs streaming stores: clean writeback drain (R8 win)
//   - int4-vectorized index loads
// Converged model: mixed DRAM-write/L2 floor (~68MB compulsory writes at
// ~3.8 TB/s effective + ~67MB L2-served reads). MLP forcing (asm, cp.async),
// sw pipelining, __ldcg, redux all measured neutral-to-negative.
// d_in[0]: int32 indices, 16384 tokens
// d_in[1]: float32 embedding table, (50257, 1024)
// d_out  : float32 (16384, 1024)

#define F        1024
#define TOK_CTA  16

__device__ __forceinline__ float2 fp4_pair(float x, float y, float inv) {
    float2 a = make_float2(x * inv, y * inv);
    __nv_fp4x2_storage_t p =
        __nv_cvt_float2_to_fp4x2(a, __NV_E2M1, cudaRoundNearest);
    __half2_raw hr = __nv_cvt_fp4x2_to_halfraw2(p, __NV_E2M1);
    __half2 h = *reinterpret_cast<__half2*>(&hr);
    return __half22float2(h);                      // exact grid values
}

__global__ void __launch_bounds__(256)
mxfp4_embed_kernel(const int* __restrict__ idx,
                   const float* __restrict__ emb,
                   float* __restrict__ out) {
    const int t = threadIdx.x;                      // one float4 of a row
    const int base = blockIdx.x * TOK_CTA;

    // vectorized uniform index loads (L1 broadcast): 4x LDG.128
    int rows[TOK_CTA];
    #pragma unroll
    for (int j = 0; j < TOK_CTA / 4; j++) {
        int4 r4 = __ldg(reinterpret_cast<const int4*>(idx + base) + j);
        rows[j * 4 + 0] = r4.x;
        rows[j * 4 + 1] = r4.y;
        rows[j * 4 + 2] = r4.z;
        rows[j * 4 + 3] = r4.w;
    }

    float4* dst = reinterpret_cast<float4*>(out) + (size_t)base * (F / 4) + t;

    #pragma unroll
    for (int j = 0; j < TOK_CTA; j++) {
        float4 v = __ldg(reinterpret_cast<const float4*>(emb) +
                         (size_t)rows[j] * (F / 4) + t);

        // max |.| over this thread's 4 values, then the 8-lane block group
        float m = fmaxf(fmaxf(fabsf(v.x), fabsf(v.y)),
                        fmaxf(fabsf(v.z), fabsf(v.w)));
        #pragma unroll
        for (int o = 4; o > 0; o >>= 1)
            m = fmaxf(m, __shfl_xor_sync(0xFFFFFFFFu, m, o, 8));

        const float sc  = (m == 0.0f) ? 1.0f : m * (1.0f / 6.0f);
        const float inv = (m == 0.0f) ? 0.0f : __fdividef(6.0f, m);

        float2 g0 = fp4_pair(v.x, v.y, inv);
        float2 g1 = fp4_pair(v.z, v.w, inv);

        float4 r;
        r.x = g0.x * sc;
        r.y = g0.y * sc;
        r.z = g1.x * sc;
        r.w = g1.y * sc;

        // streaming store: evict-first, clean writeback drain
        __stcs(dst + (size_t)j * (F / 4), r);
    }
}

extern "C" void kernel_launch(void* const* d_in, const int* in_sizes, int n_in,
                              void* d_out, int out_size) {
    const int*   idx = (const int*)d_in[0];
    const float* emb = (const float*)d_in[1];
    float*       out = (float*)d_out;

    const int tokens = in_sizes[0];              // 16384
    mxfp4_embed_kernel<<<tokens / TOK_CTA, 256>>>(idx, emb, out);
}